// round 15
// baseline (speedup 1.0000x reference)
#include <cuda_runtime.h>
#include <cuda_fp16.h>
#include <cstdint>

// B=4, C=64, H=W=128, O=64, K=3, pad=1, stride=1
#define BATCH 4
#define CH    64
#define HH    128
#define WW    128
#define HW    16384
#define NPIX  65536
#define OCH   64
#define KK    9

// Scratch (__device__ globals; no cudaMalloc allowed)
__device__ __align__(16) __half g_xh[BATCH * HW * CH];      // NHWC x, fp16, 8 MB
__device__ __align__(16) float  g_off[NPIX * 20];           // pixel-major offsets
__device__ __align__(16) __half g_wh[KK * OCH * CH];        // deform weight hi [k][oc][c]
__device__ __align__(16) __half g_wl[KK * OCH * CH];        // deform weight lo
__device__ __align__(16) __half g_owh[KK * 32 * CH];        // offset weight fp16 [k][j(32)][c]

static __device__ __forceinline__ unsigned smem_u32(const void* p) {
    unsigned a;
    asm("{ .reg .u64 t; cvta.to.shared.u64 t, %1; cvt.u32.u64 %0, t; }" : "=r"(a) : "l"(p));
    return a;
}
static __device__ __forceinline__ void ldsm4(unsigned* r, unsigned addr) {
    asm volatile("ldmatrix.sync.aligned.m8n8.x4.shared.b16 {%0,%1,%2,%3}, [%4];"
        : "=r"(r[0]), "=r"(r[1]), "=r"(r[2]), "=r"(r[3]) : "r"(addr));
}
static __device__ __forceinline__ void mma_f16(float* d, const unsigned* a,
                                               unsigned b0, unsigned b1) {
    asm volatile("mma.sync.aligned.m16n8k16.row.col.f32.f16.f16.f32 "
        "{%0,%1,%2,%3}, {%4,%5,%6,%7}, {%8,%9}, {%0,%1,%2,%3};"
        : "+f"(d[0]), "+f"(d[1]), "+f"(d[2]), "+f"(d[3])
        : "r"(a[0]), "r"(a[1]), "r"(a[2]), "r"(a[3]), "r"(b0), "r"(b1));
}

// ---------------- Kernel 0: NCHW fp32 -> NHWC fp16 ----------------
__global__ void k_transpose(const float* __restrict__ x) {
    __shared__ float tile[8][33];
    int bid = blockIdx.x;
    int b  = bid >> 9;
    int p0 = (bid & 511) << 5;
    int tx = threadIdx.x & 31, ty = threadIdx.x >> 5;
    int cx = threadIdx.x & 7,  pw = threadIdx.x >> 3;
    for (int c0 = 0; c0 < CH; c0 += 8) {
        tile[ty][tx] = x[(((size_t)(b * CH + c0 + ty)) << 14) + p0 + tx];
        __syncthreads();
        g_xh[(((size_t)((b << 14) + p0 + pw)) << 6) + c0 + cx] =
            __float2half_rn(tile[cx][pw]);
        __syncthreads();
    }
}

// ---------------- Kernel 0b: merged weight prep ----------------
// i < 36864: deform weight split hi/lo [k][oc][c]; else offset weight fp16 [k][j(32)][c]
__global__ void k_wprep(const float* __restrict__ w, const float* __restrict__ ow) {
    int i = blockIdx.x * 256 + threadIdx.x;
    if (i < KK * OCH * CH) {
        int k = i / (OCH * CH), r = i % (OCH * CH);
        int oc = r >> 6, c = r & 63;
        float v = w[(oc * CH + c) * KK + k];
        __half h = __float2half_rn(v);
        g_wh[i] = h;
        g_wl[i] = __float2half_rn(v - __half2float(h));
    } else {
        int j2 = i - KK * OCH * CH;
        if (j2 < KK * 32 * CH) {
            int k = j2 / (32 * CH), r = j2 % (32 * CH);
            int j = r >> 6, c = r & 63;
            float v = (j < 18) ? ow[(j * CH + c) * 9 + k] : 0.f;
            g_owh[j2] = __float2half_rn(v);
        }
    }
}

// ---------------- Kernel 1: offset conv via fp16 HMMA (single weight pass) ----------------
#define OS_A  0
#define OS_BH 16640
#define OS_TOT 20736

__global__ __launch_bounds__(128, 6) void k_offmma(const float* __restrict__ offb) {
    __shared__ __align__(128) char smem2[OS_TOT];
    unsigned sb = smem_u32(smem2);

    int t = threadIdx.x, l = t & 31, w = t >> 5;
    int bx = blockIdx.x;
    int b  = bx >> 7, y = bx & 127;
    int pix0 = y << 7;

    float acc[2][4][4];
#pragma unroll
    for (int mi = 0; mi < 2; mi++)
#pragma unroll
        for (int ni = 0; ni < 4; ni++)
#pragma unroll
            for (int j = 0; j < 4; j++) acc[mi][ni][j] = 0.f;

    int arow  = (l & 7) | (l & 8);
    int ahalf = (l >> 4) & 1;
    int brow  = (((l >> 4) & 1) << 3) | (l & 7);
    int bhalf = (l >> 3) & 1;

    // zero halo rows (tile rows 0 and 129)
    if (t < 16) {
        int rr = (t >> 3) ? 129 : 0;
        int ch = t & 7;
        *(uint4*)(smem2 + OS_A + rr * 128 + ch * 16) = make_uint4(0, 0, 0, 0);
    }

#pragma unroll 1
    for (int dyi = 0; dyi < 3; dyi++) {
        int row = y + dyi - 1;
        if ((unsigned)row >= (unsigned)HH) continue;
        __syncthreads();
        // ---- fill A rows 1..128: straight swizzled copy of fp16 row ----
        const uint4* src = (const uint4*)g_xh +
                           (((size_t)((b << 14) + (row << 7))) << 3);
#pragma unroll
        for (int it = 0; it < 8; it++) {
            int idx = it * 128 + t;
            int pxl = idx >> 3, ch = idx & 7;
            int r1 = pxl + 1;
            int dst = r1 * 128 + ((ch ^ (r1 & 7)) << 4);
            *(uint4*)(smem2 + OS_A + dst) = src[idx];
        }
#pragma unroll 1
        for (int dxi = 0; dxi < 3; dxi++) {
            int k = dyi * 3 + dxi;
            __syncthreads();
            // ---- B tap tile (32 x 64 fp16, 256 uint4) ----
            {
                const uint4* bh4 = (const uint4*)(g_owh + k * (32 * CH));
#pragma unroll
                for (int u0 = 0; u0 < 2; u0++) {
                    int u = u0 * 128 + t;
                    int rowb = u >> 3, ch = u & 7;
                    int dst = rowb * 128 + ((ch ^ (rowb & 7)) << 4);
                    *(uint4*)(smem2 + OS_BH + dst) = bh4[u];
                }
            }
            __syncthreads();
            // ---- MMA: single pass over K=64 ----
#pragma unroll
            for (int ks = 0; ks < 4; ks++) {
                unsigned ah[2][4];
#pragma unroll
                for (int mi = 0; mi < 2; mi++) {
                    int tr = w * 32 + mi * 16 + arow + dxi;
                    unsigned ad = sb + OS_A + tr * 128 +
                                  ((((ks << 1) + ahalf) ^ (tr & 7)) << 4);
                    ldsm4(ah[mi], ad);
                }
#pragma unroll
                for (int np = 0; np < 2; np++) {
                    int rowb = np * 16 + brow;
                    unsigned bd = sb + OS_BH + rowb * 128 +
                                  ((((ks << 1) + bhalf) ^ (rowb & 7)) << 4);
                    unsigned bh[4];
                    ldsm4(bh, bd);
#pragma unroll
                    for (int mi = 0; mi < 2; mi++) {
#pragma unroll
                        for (int nt = 0; nt < 2; nt++) {
                            float* d = acc[mi][np * 2 + nt];
                            mma_f16(d, ah[mi], bh[2 * nt], bh[2 * nt + 1]);
                        }
                    }
                }
            }
        }
    }

    // ---- epilogue: regs -> smem [128px][20] -> g_off ----
    __syncthreads();
    float* st = (float*)smem2;
#pragma unroll
    for (int mi = 0; mi < 2; mi++)
#pragma unroll
        for (int ni = 0; ni < 3; ni++) {
            int row0 = w * 32 + mi * 16 + (l >> 2);
            int col  = ni * 8 + (l & 3) * 2;
            if (col < 18) {
                float b0 = offb[col], b1 = offb[col + 1];
                st[row0 * 20 + col]           = acc[mi][ni][0] + b0;
                st[row0 * 20 + col + 1]       = acc[mi][ni][1] + b1;
                st[(row0 + 8) * 20 + col]     = acc[mi][ni][2] + b0;
                st[(row0 + 8) * 20 + col + 1] = acc[mi][ni][3] + b1;
            }
        }
    __syncthreads();
    float4* dst = (float4*)(g_off + (size_t)((b << 14) + pix0) * 20);
    const float4* s4 = (const float4*)st;
#pragma unroll
    for (int it = 0; it < 5; it++)
        dst[it * 128 + t] = s4[it * 128 + t];
}

// ---------------- Kernel 2: deformable conv, fp16 datapath ----------------
// Block = 1 row (128 px), 128 threads, 4 warps (32px x 64oc each), 5 CTAs/SM.
#define SM_A    0
#define SM_BH   16384
#define SM_BL   24576
#define SM_SET  32768
#define SMEM_D_TOT 36864

__global__ __launch_bounds__(128, 5) void k_deform(const float* __restrict__ bias,
                                                   float* __restrict__ out) {
    __shared__ __align__(1024) char smem[SMEM_D_TOT];
    unsigned sb = smem_u32(smem);
    float* s_set = (float*)(smem + SM_SET);

    int t = threadIdx.x, l = t & 31, w = t >> 5;
    int bx = blockIdx.x;
    int b  = bx >> 7, y = bx & 127;
    int pix0 = y << 7;

    const __half* xh = g_xh + ((size_t)b << 20);
    const float* offbase = g_off + (size_t)((b << 14) + pix0) * 20;

    float acc[2][8][4];
#pragma unroll
    for (int mi = 0; mi < 2; mi++)
#pragma unroll
        for (int ni = 0; ni < 8; ni++)
#pragma unroll
            for (int j = 0; j < 4; j++) acc[mi][ni][j] = 0.f;

    int arow  = (l & 7) | (l & 8);
    int ahalf = (l >> 4) & 1;
    int brow  = (((l >> 4) & 1) << 3) | (l & 7);
    int bhalf = (l >> 3) & 1;

#pragma unroll 1
    for (int k = 0; k < KK; k++) {
        __syncthreads();
        // ---- bilinear setup (thread = pixel) ----
        {
            float2 o = *(const float2*)(offbase + t * 20 + 2 * k);
            float py  = (float)(y + k / 3 - 1) + o.x;
            float pxf = (float)(t + k % 3 - 1) + o.y;
            float fy0 = floorf(py), fx0 = floorf(pxf);
            int yA = (int)fy0, xA = (int)fx0;
            int yB = yA + 1,   xB = xA + 1;
            float wy1 = py - fy0, wx1 = pxf - fx0;
            float wy0 = 1.f - wy1, wx0 = 1.f - wx1;
            bool vy0 = (unsigned)yA < (unsigned)HH, vy1 = (unsigned)yB < (unsigned)HH;
            bool vx0 = (unsigned)xA < (unsigned)WW, vx1 = (unsigned)xB < (unsigned)WW;
            s_set[0 * 128 + t] = (vy0 && vx0) ? wy0 * wx0 : 0.f;
            s_set[1 * 128 + t] = (vy0 && vx1) ? wy0 * wx1 : 0.f;
            s_set[2 * 128 + t] = (vy1 && vx0) ? wy1 * wx0 : 0.f;
            s_set[3 * 128 + t] = (vy1 && vx1) ? wy1 * wx1 : 0.f;
            int cy0 = min(max(yA, 0), HH - 1), cy1 = min(max(yB, 0), HH - 1);
            int cx0 = min(max(xA, 0), WW - 1), cx1 = min(max(xB, 0), WW - 1);
            s_set[4 * 128 + t] = __int_as_float(((cy0 << 7) + cx0) << 6);
            s_set[5 * 128 + t] = __int_as_float(((cy0 << 7) + cx1) << 6);
            s_set[6 * 128 + t] = __int_as_float(((cy1 << 7) + cx0) << 6);
            s_set[7 * 128 + t] = __int_as_float(((cy1 << 7) + cx1) << 6);
        }
        // ---- B tiles: 8KB hi + 8KB lo (512 uint4 each) ----
        {
            const uint4* srcH = (const uint4*)(g_wh + k * (OCH * CH));
            const uint4* srcL = (const uint4*)(g_wl + k * (OCH * CH));
#pragma unroll
            for (int u0 = 0; u0 < 4; u0++) {
                int idx = u0 * 128 + t;
                int row = idx >> 3, ch = idx & 7;
                int dst = row * 128 + ((ch ^ (row & 7)) << 4);
                *(uint4*)(smem + SM_BH + dst) = srcH[idx];
                *(uint4*)(smem + SM_BL + dst) = srcL[idx];
            }
        }
        __syncthreads();
        // ---- gather fp16 corners (1 line each), blend fp32, store fp16 A ----
#pragma unroll
        for (int it = 0; it < 8; it++) {
            int slot = it * 128 + t;
            int pxl = slot >> 3, cg = slot & 7;
            float w00 = s_set[0 * 128 + pxl], w01 = s_set[1 * 128 + pxl];
            float w10 = s_set[2 * 128 + pxl], w11 = s_set[3 * 128 + pxl];
            int i00 = __float_as_int(s_set[4 * 128 + pxl]);
            int i01 = __float_as_int(s_set[5 * 128 + pxl]);
            int i10 = __float_as_int(s_set[6 * 128 + pxl]);
            int i11 = __float_as_int(s_set[7 * 128 + pxl]);
            uint4 qa = *((const uint4*)(xh + i00) + cg);
            uint4 qb = *((const uint4*)(xh + i01) + cg);
            uint4 qc = *((const uint4*)(xh + i10) + cg);
            uint4 qd = *((const uint4*)(xh + i11) + cg);
            const __half2* ha = (const __half2*)&qa;
            const __half2* hb = (const __half2*)&qb;
            const __half2* hc = (const __half2*)&qc;
            const __half2* hd = (const __half2*)&qd;
            uint4 oq;
            unsigned* op = (unsigned*)&oq;
#pragma unroll
            for (int j = 0; j < 4; j++) {
                float2 fa = __half22float2(ha[j]);
                float2 fb = __half22float2(hb[j]);
                float2 fc = __half22float2(hc[j]);
                float2 fd = __half22float2(hd[j]);
                float2 r;
                r.x = fmaf(w11, fd.x, fmaf(w10, fc.x, fmaf(w01, fb.x, w00 * fa.x)));
                r.y = fmaf(w11, fd.y, fmaf(w10, fc.y, fmaf(w01, fb.y, w00 * fa.y)));
                __half2 h = __float22half2_rn(r);
                op[j] = *(unsigned*)&h;
            }
            int dst = pxl * 128 + ((cg ^ (pxl & 7)) << 4);
            *(uint4*)(smem + SM_A + dst) = oq;
        }
        __syncthreads();
        // ---- tensor passes: ABh + ABl, K=64 ----
#pragma unroll
        for (int ks = 0; ks < 4; ks++) {
            unsigned ah[2][4];
#pragma unroll
            for (int mi = 0; mi < 2; mi++) {
                int row = w * 32 + mi * 16 + arow;
                unsigned ad = sb + SM_A + row * 128 +
                              ((((ks << 1) + ahalf) ^ (row & 7)) << 4);
                ldsm4(ah[mi], ad);
            }
#pragma unroll
            for (int np = 0; np < 4; np++) {
                int rowb = np * 16 + brow;
                unsigned bd = sb + SM_BH + rowb * 128 +
                              ((((ks << 1) + bhalf) ^ (rowb & 7)) << 4);
                unsigned bh[4], bl[4];
                ldsm4(bh, bd);
                ldsm4(bl, bd + 8192);
#pragma unroll
                for (int mi = 0; mi < 2; mi++) {
#pragma unroll
                    for (int nt = 0; nt < 2; nt++) {
                        float* d = acc[mi][np * 2 + nt];
                        mma_f16(d, ah[mi], bh[2 * nt], bh[2 * nt + 1]);
                        mma_f16(d, ah[mi], bl[2 * nt], bl[2 * nt + 1]);
                    }
                }
            }
        }
    }

    // ---- epilogue: regs -> smem [oc][128px] -> coalesced NCHW stores ----
    __syncthreads();
    float* sp = (float*)smem;   // pitch 132 floats
#pragma unroll
    for (int mi = 0; mi < 2; mi++)
#pragma unroll
        for (int ni = 0; ni < 8; ni++) {
            int row = w * 32 + mi * 16 + (l >> 2);
            int col = ni * 8 + (l & 3) * 2;
            float b0 = bias[col], b1 = bias[col + 1];
            sp[col * 132 + row]           = acc[mi][ni][0] + b0;
            sp[(col + 1) * 132 + row]     = acc[mi][ni][1] + b1;
            sp[col * 132 + row + 8]       = acc[mi][ni][2] + b0;
            sp[(col + 1) * 132 + row + 8] = acc[mi][ni][3] + b1;
        }
    __syncthreads();
    float* ob = out + (((size_t)b << 6) << 14) + pix0;
#pragma unroll
    for (int it = 0; it < 64; it++) {
        int i = it * 128 + t;
        int oc = i >> 7, px = i & 127;
        ob[((size_t)oc << 14) + px] = sp[oc * 132 + px];
    }
}

extern "C" void kernel_launch(void* const* d_in, const int* in_sizes, int n_in,
                              void* d_out, int out_size) {
    const float* x      = (const float*)d_in[0];
    const float* offw   = (const float*)d_in[1];
    const float* offb   = (const float*)d_in[2];
    const float* weight = (const float*)d_in[3];
    const float* bias   = (const float*)d_in[4];
    float* out = (float*)d_out;

    k_transpose<<<2048, 256>>>(x);
    k_wprep<<<(KK * OCH * CH + KK * 32 * CH + 255) / 256, 256>>>(weight, offw);
    k_offmma<<<512, 128>>>(offb);
    k_deform<<<512, 128>>>(bias, out);
}

// round 16
// speedup vs baseline: 1.1874x; 1.1874x over previous
#include <cuda_runtime.h>
#include <cuda_fp16.h>
#include <cstdint>

// B=4, C=64, H=W=128, O=64, K=3, pad=1, stride=1
#define BATCH 4
#define CH    64
#define HH    128
#define WW    128
#define HW    16384
#define NPIX  65536
#define OCH   64
#define KK    9

// Scratch (__device__ globals; no cudaMalloc allowed)
__device__ __align__(16) __half g_xh[BATCH * HW * CH];      // NHWC x, fp16, 8 MB
__device__ __align__(16) float  g_off[NPIX * 20];           // pixel-major offsets
__device__ __align__(16) __half g_wh[KK * OCH * CH];        // deform weight hi [k][oc][c]
__device__ __align__(16) __half g_wl[KK * OCH * CH];        // deform weight lo
__device__ __align__(16) __half g_owh[KK * 32 * CH];        // offset weight fp16 [k][j(32)][c]

static __device__ __forceinline__ unsigned smem_u32(const void* p) {
    unsigned a;
    asm("{ .reg .u64 t; cvta.to.shared.u64 t, %1; cvt.u32.u64 %0, t; }" : "=r"(a) : "l"(p));
    return a;
}
static __device__ __forceinline__ void ldsm4(unsigned* r, unsigned addr) {
    asm volatile("ldmatrix.sync.aligned.m8n8.x4.shared.b16 {%0,%1,%2,%3}, [%4];"
        : "=r"(r[0]), "=r"(r[1]), "=r"(r[2]), "=r"(r[3]) : "r"(addr));
}
static __device__ __forceinline__ void mma_f16(float* d, const unsigned* a,
                                               unsigned b0, unsigned b1) {
    asm volatile("mma.sync.aligned.m16n8k16.row.col.f32.f16.f16.f32 "
        "{%0,%1,%2,%3}, {%4,%5,%6,%7}, {%8,%9}, {%0,%1,%2,%3};"
        : "+f"(d[0]), "+f"(d[1]), "+f"(d[2]), "+f"(d[3])
        : "r"(a[0]), "r"(a[1]), "r"(a[2]), "r"(a[3]), "r"(b0), "r"(b1));
}

// ---------------- Kernel 0: NCHW fp32 -> NHWC fp16 ----------------
__global__ void k_transpose(const float* __restrict__ x) {
    __shared__ float tile[8][33];
    int bid = blockIdx.x;
    int b  = bid >> 9;
    int p0 = (bid & 511) << 5;
    int tx = threadIdx.x & 31, ty = threadIdx.x >> 5;
    int cx = threadIdx.x & 7,  pw = threadIdx.x >> 3;
    for (int c0 = 0; c0 < CH; c0 += 8) {
        tile[ty][tx] = x[(((size_t)(b * CH + c0 + ty)) << 14) + p0 + tx];
        __syncthreads();
        g_xh[(((size_t)((b << 14) + p0 + pw)) << 6) + c0 + cx] =
            __float2half_rn(tile[cx][pw]);
        __syncthreads();
    }
}

// ---------------- Kernel 0b: merged weight prep ----------------
__global__ void k_wprep(const float* __restrict__ w, const float* __restrict__ ow) {
    int i = blockIdx.x * 256 + threadIdx.x;
    if (i < KK * OCH * CH) {
        int k = i / (OCH * CH), r = i % (OCH * CH);
        int oc = r >> 6, c = r & 63;
        float v = w[(oc * CH + c) * KK + k];
        __half h = __float2half_rn(v);
        g_wh[i] = h;
        g_wl[i] = __float2half_rn(v - __half2float(h));
    } else {
        int j2 = i - KK * OCH * CH;
        if (j2 < KK * 32 * CH) {
            int k = j2 / (32 * CH), r = j2 % (32 * CH);
            int j = r >> 6, c = r & 63;
            float v = (j < 18) ? ow[(j * CH + c) * 9 + k] : 0.f;
            g_owh[j2] = __float2half_rn(v);
        }
    }
}

// ---------------- Kernel 1: offset conv via fp16 HMMA (single weight pass) ----------------
#define OS_A  0
#define OS_BH 16640
#define OS_TOT 20736

__global__ __launch_bounds__(128, 6) void k_offmma(const float* __restrict__ offb) {
    __shared__ __align__(128) char smem2[OS_TOT];
    unsigned sb = smem_u32(smem2);

    int t = threadIdx.x, l = t & 31, w = t >> 5;
    int bx = blockIdx.x;
    int b  = bx >> 7, y = bx & 127;
    int pix0 = y << 7;

    float acc[2][4][4];
#pragma unroll
    for (int mi = 0; mi < 2; mi++)
#pragma unroll
        for (int ni = 0; ni < 4; ni++)
#pragma unroll
            for (int j = 0; j < 4; j++) acc[mi][ni][j] = 0.f;

    int arow  = (l & 7) | (l & 8);
    int ahalf = (l >> 4) & 1;
    int brow  = (((l >> 4) & 1) << 3) | (l & 7);
    int bhalf = (l >> 3) & 1;

    // zero halo rows (tile rows 0 and 129)
    if (t < 16) {
        int rr = (t >> 3) ? 129 : 0;
        int ch = t & 7;
        *(uint4*)(smem2 + OS_A + rr * 128 + ch * 16) = make_uint4(0, 0, 0, 0);
    }

#pragma unroll 1
    for (int dyi = 0; dyi < 3; dyi++) {
        int row = y + dyi - 1;
        if ((unsigned)row >= (unsigned)HH) continue;
        __syncthreads();
        // ---- fill A rows 1..128: straight swizzled copy of fp16 row ----
        const uint4* src = (const uint4*)g_xh +
                           (((size_t)((b << 14) + (row << 7))) << 3);
#pragma unroll
        for (int it = 0; it < 8; it++) {
            int idx = it * 128 + t;
            int pxl = idx >> 3, ch = idx & 7;
            int r1 = pxl + 1;
            int dst = r1 * 128 + ((ch ^ (r1 & 7)) << 4);
            *(uint4*)(smem2 + OS_A + dst) = src[idx];
        }
#pragma unroll 1
        for (int dxi = 0; dxi < 3; dxi++) {
            int k = dyi * 3 + dxi;
            __syncthreads();
            // ---- B tap tile (32 x 64 fp16, 256 uint4) ----
            {
                const uint4* bh4 = (const uint4*)(g_owh + k * (32 * CH));
#pragma unroll
                for (int u0 = 0; u0 < 2; u0++) {
                    int u = u0 * 128 + t;
                    int rowb = u >> 3, ch = u & 7;
                    int dst = rowb * 128 + ((ch ^ (rowb & 7)) << 4);
                    *(uint4*)(smem2 + OS_BH + dst) = bh4[u];
                }
            }
            __syncthreads();
            // ---- MMA: single pass over K=64 ----
#pragma unroll
            for (int ks = 0; ks < 4; ks++) {
                unsigned ah[2][4];
#pragma unroll
                for (int mi = 0; mi < 2; mi++) {
                    int tr = w * 32 + mi * 16 + arow + dxi;
                    unsigned ad = sb + OS_A + tr * 128 +
                                  ((((ks << 1) + ahalf) ^ (tr & 7)) << 4);
                    ldsm4(ah[mi], ad);
                }
#pragma unroll
                for (int np = 0; np < 2; np++) {
                    int rowb = np * 16 + brow;
                    unsigned bd = sb + OS_BH + rowb * 128 +
                                  ((((ks << 1) + bhalf) ^ (rowb & 7)) << 4);
                    unsigned bh[4];
                    ldsm4(bh, bd);
#pragma unroll
                    for (int mi = 0; mi < 2; mi++) {
#pragma unroll
                        for (int nt = 0; nt < 2; nt++) {
                            float* d = acc[mi][np * 2 + nt];
                            mma_f16(d, ah[mi], bh[2 * nt], bh[2 * nt + 1]);
                        }
                    }
                }
            }
        }
    }

    // ---- epilogue: regs -> smem [128px][20] -> g_off ----
    __syncthreads();
    float* st = (float*)smem2;
#pragma unroll
    for (int mi = 0; mi < 2; mi++)
#pragma unroll
        for (int ni = 0; ni < 3; ni++) {
            int row0 = w * 32 + mi * 16 + (l >> 2);
            int col  = ni * 8 + (l & 3) * 2;
            if (col < 18) {
                float b0 = offb[col], b1 = offb[col + 1];
                st[row0 * 20 + col]           = acc[mi][ni][0] + b0;
                st[row0 * 20 + col + 1]       = acc[mi][ni][1] + b1;
                st[(row0 + 8) * 20 + col]     = acc[mi][ni][2] + b0;
                st[(row0 + 8) * 20 + col + 1] = acc[mi][ni][3] + b1;
            }
        }
    __syncthreads();
    float4* dst = (float4*)(g_off + (size_t)((b << 14) + pix0) * 20);
    const float4* s4 = (const float4*)st;
#pragma unroll
    for (int it = 0; it < 5; it++)
        dst[it * 128 + t] = s4[it * 128 + t];
}

// ---------------- Kernel 2: deformable conv, fp16 datapath (R13 config) ----------------
// Block = 1 row (128 px), 128 threads, 4 warps (32px x 64oc each), 4 CTAs/SM.
#define SM_A    0
#define SM_BH   16384
#define SM_BL   24576
#define SM_SET  32768
#define SMEM_D_TOT 36864

__global__ __launch_bounds__(128, 4) void k_deform(const float* __restrict__ bias,
                                                   float* __restrict__ out) {
    __shared__ __align__(1024) char smem[SMEM_D_TOT];
    unsigned sb = smem_u32(smem);
    float* s_set = (float*)(smem + SM_SET);

    int t = threadIdx.x, l = t & 31, w = t >> 5;
    int bx = blockIdx.x;
    int b  = bx >> 7, y = bx & 127;
    int pix0 = y << 7;

    const __half* xh = g_xh + ((size_t)b << 20);
    const float* offbase = g_off + (size_t)((b << 14) + pix0) * 20;

    float acc[2][8][4];
#pragma unroll
    for (int mi = 0; mi < 2; mi++)
#pragma unroll
        for (int ni = 0; ni < 8; ni++)
#pragma unroll
            for (int j = 0; j < 4; j++) acc[mi][ni][j] = 0.f;

    int arow  = (l & 7) | (l & 8);
    int ahalf = (l >> 4) & 1;
    int brow  = (((l >> 4) & 1) << 3) | (l & 7);
    int bhalf = (l >> 3) & 1;

#pragma unroll 1
    for (int k = 0; k < KK; k++) {
        __syncthreads();
        // ---- bilinear setup (thread = pixel) ----
        {
            float2 o = *(const float2*)(offbase + t * 20 + 2 * k);
            float py  = (float)(y + k / 3 - 1) + o.x;
            float pxf = (float)(t + k % 3 - 1) + o.y;
            float fy0 = floorf(py), fx0 = floorf(pxf);
            int yA = (int)fy0, xA = (int)fx0;
            int yB = yA + 1,   xB = xA + 1;
            float wy1 = py - fy0, wx1 = pxf - fx0;
            float wy0 = 1.f - wy1, wx0 = 1.f - wx1;
            bool vy0 = (unsigned)yA < (unsigned)HH, vy1 = (unsigned)yB < (unsigned)HH;
            bool vx0 = (unsigned)xA < (unsigned)WW, vx1 = (unsigned)xB < (unsigned)WW;
            s_set[0 * 128 + t] = (vy0 && vx0) ? wy0 * wx0 : 0.f;
            s_set[1 * 128 + t] = (vy0 && vx1) ? wy0 * wx1 : 0.f;
            s_set[2 * 128 + t] = (vy1 && vx0) ? wy1 * wx0 : 0.f;
            s_set[3 * 128 + t] = (vy1 && vx1) ? wy1 * wx1 : 0.f;
            int cy0 = min(max(yA, 0), HH - 1), cy1 = min(max(yB, 0), HH - 1);
            int cx0 = min(max(xA, 0), WW - 1), cx1 = min(max(xB, 0), WW - 1);
            s_set[4 * 128 + t] = __int_as_float(((cy0 << 7) + cx0) << 6);
            s_set[5 * 128 + t] = __int_as_float(((cy0 << 7) + cx1) << 6);
            s_set[6 * 128 + t] = __int_as_float(((cy1 << 7) + cx0) << 6);
            s_set[7 * 128 + t] = __int_as_float(((cy1 << 7) + cx1) << 6);
        }
        // ---- B tiles: 8KB hi + 8KB lo (512 uint4 each) ----
        {
            const uint4* srcH = (const uint4*)(g_wh + k * (OCH * CH));
            const uint4* srcL = (const uint4*)(g_wl + k * (OCH * CH));
#pragma unroll
            for (int u0 = 0; u0 < 4; u0++) {
                int idx = u0 * 128 + t;
                int row = idx >> 3, ch = idx & 7;
                int dst = row * 128 + ((ch ^ (row & 7)) << 4);
                *(uint4*)(smem + SM_BH + dst) = srcH[idx];
                *(uint4*)(smem + SM_BL + dst) = srcL[idx];
            }
        }
        __syncthreads();
        // ---- gather fp16 corners (1 line each), blend fp32, store fp16 A ----
#pragma unroll
        for (int it = 0; it < 8; it++) {
            int slot = it * 128 + t;
            int pxl = slot >> 3, cg = slot & 7;
            float w00 = s_set[0 * 128 + pxl], w01 = s_set[1 * 128 + pxl];
            float w10 = s_set[2 * 128 + pxl], w11 = s_set[3 * 128 + pxl];
            int i00 = __float_as_int(s_set[4 * 128 + pxl]);
            int i01 = __float_as_int(s_set[5 * 128 + pxl]);
            int i10 = __float_as_int(s_set[6 * 128 + pxl]);
            int i11 = __float_as_int(s_set[7 * 128 + pxl]);
            uint4 qa = *((const uint4*)(xh + i00) + cg);
            uint4 qb = *((const uint4*)(xh + i01) + cg);
            uint4 qc = *((const uint4*)(xh + i10) + cg);
            uint4 qd = *((const uint4*)(xh + i11) + cg);
            const __half2* ha = (const __half2*)&qa;
            const __half2* hb = (const __half2*)&qb;
            const __half2* hc = (const __half2*)&qc;
            const __half2* hd = (const __half2*)&qd;
            uint4 oq;
            unsigned* op = (unsigned*)&oq;
#pragma unroll
            for (int j = 0; j < 4; j++) {
                float2 fa = __half22float2(ha[j]);
                float2 fb = __half22float2(hb[j]);
                float2 fc = __half22float2(hc[j]);
                float2 fd = __half22float2(hd[j]);
                float2 r;
                r.x = fmaf(w11, fd.x, fmaf(w10, fc.x, fmaf(w01, fb.x, w00 * fa.x)));
                r.y = fmaf(w11, fd.y, fmaf(w10, fc.y, fmaf(w01, fb.y, w00 * fa.y)));
                __half2 h = __float22half2_rn(r);
                op[j] = *(unsigned*)&h;
            }
            int dst = pxl * 128 + ((cg ^ (pxl & 7)) << 4);
            *(uint4*)(smem + SM_A + dst) = oq;
        }
        __syncthreads();
        // ---- tensor passes: ABh + ABl, K=64 ----
#pragma unroll
        for (int ks = 0; ks < 4; ks++) {
            unsigned ah[2][4];
#pragma unroll
            for (int mi = 0; mi < 2; mi++) {
                int row = w * 32 + mi * 16 + arow;
                unsigned ad = sb + SM_A + row * 128 +
                              ((((ks << 1) + ahalf) ^ (row & 7)) << 4);
                ldsm4(ah[mi], ad);
            }
#pragma unroll
            for (int np = 0; np < 4; np++) {
                int rowb = np * 16 + brow;
                unsigned bd = sb + SM_BH + rowb * 128 +
                              ((((ks << 1) + bhalf) ^ (rowb & 7)) << 4);
                unsigned bh[4], bl[4];
                ldsm4(bh, bd);
                ldsm4(bl, bd + 8192);
#pragma unroll
                for (int mi = 0; mi < 2; mi++) {
#pragma unroll
                    for (int nt = 0; nt < 2; nt++) {
                        float* d = acc[mi][np * 2 + nt];
                        mma_f16(d, ah[mi], bh[2 * nt], bh[2 * nt + 1]);
                        mma_f16(d, ah[mi], bl[2 * nt], bl[2 * nt + 1]);
                    }
                }
            }
        }
    }

    // ---- epilogue: regs -> smem [oc][128px] -> coalesced NCHW stores ----
    __syncthreads();
    float* sp = (float*)smem;   // pitch 132 floats
#pragma unroll
    for (int mi = 0; mi < 2; mi++)
#pragma unroll
        for (int ni = 0; ni < 8; ni++) {
            int row = w * 32 + mi * 16 + (l >> 2);
            int col = ni * 8 + (l & 3) * 2;
            float b0 = bias[col], b1 = bias[col + 1];
            sp[col * 132 + row]           = acc[mi][ni][0] + b0;
            sp[(col + 1) * 132 + row]     = acc[mi][ni][1] + b1;
            sp[col * 132 + row + 8]       = acc[mi][ni][2] + b0;
            sp[(col + 1) * 132 + row + 8] = acc[mi][ni][3] + b1;
        }
    __syncthreads();
    float* ob = out + (((size_t)b << 6) << 14) + pix0;
#pragma unroll
    for (int it = 0; it < 64; it++) {
        int i = it * 128 + t;
        int oc = i >> 7, px = i & 127;
        ob[((size_t)oc << 14) + px] = sp[oc * 132 + px];
    }
}

extern "C" void kernel_launch(void* const* d_in, const int* in_sizes, int n_in,
                              void* d_out, int out_size) {
    const float* x      = (const float*)d_in[0];
    const float* offw   = (const float*)d_in[1];
    const float* offb   = (const float*)d_in[2];
    const float* weight = (const float*)d_in[3];
    const float* bias   = (const float*)d_in[4];
    float* out = (float*)d_out;

    k_transpose<<<2048, 256>>>(x);
    k_wprep<<<(KK * OCH * CH + KK * 32 * CH + 255) / 256, 256>>>(weight, offw);
    k_offmma<<<512, 128>>>(offb);
    k_deform<<<512, 128>>>(bias, out);
}